// round 7
// baseline (speedup 1.0000x reference)
#include <cuda_runtime.h>
#include <stdint.h>

#define BATCH   512
#define EMB     512
#define NCLS    100

#define KSPLIT  4
#define KSLICE  (EMB / KSPLIT)   // 128
#define BM      64
#define BN      128
#define BK      32

#define NCTA    128              // 4 x 8 x 4, must be < 148 (one wave)
#define MAXPOS  64

__device__ float    g_D[KSPLIT][BATCH * BATCH];
__device__ unsigned g_cnt;       // monotonic grid-sync counter (never reset)

__device__ __forceinline__ uint32_t f2tf32(float f) {
    uint32_t r;
    asm("cvt.rna.tf32.f32 %0, %1;" : "=r"(r) : "f"(f));
    return r;
}

// ---------------------------------------------------------------------------
// Fused kernel: phase 1 = tf32 MMA GEMM (unchanged from R6),
// grid-wide sync, phase 2 = 4 anchors' hinge per CTA.
// ---------------------------------------------------------------------------
__global__ __launch_bounds__(256) void fused_loss(const float* __restrict__ X,
                                                  const int*   __restrict__ labels,
                                                  const float* __restrict__ mu,
                                                  const float* __restrict__ nv,
                                                  float*       __restrict__ out) {
    __shared__ uint32_t As[BM][36];
    __shared__ uint32_t Bs[BN][36];
    __shared__ int      lab[BATCH];
    __shared__ float    posv[4][MAXPOS];
    __shared__ int      npos[4];
    __shared__ float    red[8];

    const int tid = threadIdx.x;
    const int bx = blockIdx.x;          // N tile (0..3)
    const int by = blockIdx.y;          // M tile (0..7)
    const int bz = blockIdx.z;          // K slice (0..3)
    const int k0 = bz * KSLICE;

    // Load labels into smem early (consumed in phase 2; barrier below covers it).
    {
        const int c0 = 2 * tid;
        *(int2*)&lab[c0] = *(const int2*)&labels[c0];
    }

    if (bx == 0 && by == 0 && bz == 0 && tid == 0) {
        float s = 0.f;
        for (int c = 0; c < NCLS; c++) s += mu[c] + nv[c];
        out[0] = -s * (1.0f / NCLS);
    }

    // ---------------- Phase 1: GEMM ----------------
    const int w    = tid >> 5;
    const int lane = tid & 31;
    const int g    = lane >> 2;
    const int tig  = lane & 3;
    const int wm   = w & 1;
    const int wn   = w >> 1;

    float4 pa[2], pb[4];
    #pragma unroll
    for (int l = 0; l < 2; l++) {
        int idx = tid + l * 256;
        int r = idx >> 3, c4 = idx & 7;
        pa[l] = *(const float4*)&X[(by * BM + r) * EMB + k0 + c4 * 4];
    }
    #pragma unroll
    for (int l = 0; l < 4; l++) {
        int idx = tid + l * 256;
        int r = idx >> 3, c4 = idx & 7;
        pb[l] = *(const float4*)&X[(bx * BN + r) * EMB + k0 + c4 * 4];
    }

    float acc[2][4][4] = {};

    #pragma unroll
    for (int kt = 0; kt < KSLICE; kt += BK) {
        #pragma unroll
        for (int l = 0; l < 2; l++) {
            int idx = tid + l * 256;
            int r = idx >> 3, c4 = idx & 7;
            uint4 t; t.x = f2tf32(pa[l].x); t.y = f2tf32(pa[l].y);
                     t.z = f2tf32(pa[l].z); t.w = f2tf32(pa[l].w);
            *(uint4*)&As[r][c4 * 4] = t;
        }
        #pragma unroll
        for (int l = 0; l < 4; l++) {
            int idx = tid + l * 256;
            int r = idx >> 3, c4 = idx & 7;
            uint4 t; t.x = f2tf32(pb[l].x); t.y = f2tf32(pb[l].y);
                     t.z = f2tf32(pb[l].z); t.w = f2tf32(pb[l].w);
            *(uint4*)&Bs[r][c4 * 4] = t;
        }
        __syncthreads();

        if (kt + BK < KSLICE) {
            #pragma unroll
            for (int l = 0; l < 2; l++) {
                int idx = tid + l * 256;
                int r = idx >> 3, c4 = idx & 7;
                pa[l] = *(const float4*)&X[(by * BM + r) * EMB + k0 + kt + BK + c4 * 4];
            }
            #pragma unroll
            for (int l = 0; l < 4; l++) {
                int idx = tid + l * 256;
                int r = idx >> 3, c4 = idx & 7;
                pb[l] = *(const float4*)&X[(bx * BN + r) * EMB + k0 + kt + BK + c4 * 4];
            }
        }

        #pragma unroll
        for (int kk = 0; kk < BK; kk += 8) {
            uint32_t a[2][4], b[4][2];
            #pragma unroll
            for (int mi = 0; mi < 2; mi++) {
                int r0 = wm * 32 + mi * 16;
                a[mi][0] = As[r0 + g    ][kk + tig];
                a[mi][1] = As[r0 + g + 8][kk + tig];
                a[mi][2] = As[r0 + g    ][kk + tig + 4];
                a[mi][3] = As[r0 + g + 8][kk + tig + 4];
            }
            #pragma unroll
            for (int ni = 0; ni < 4; ni++) {
                int n0 = wn * 32 + ni * 8;
                b[ni][0] = Bs[n0 + g][kk + tig];
                b[ni][1] = Bs[n0 + g][kk + tig + 4];
            }
            #pragma unroll
            for (int mi = 0; mi < 2; mi++)
                #pragma unroll
                for (int ni = 0; ni < 4; ni++) {
                    asm volatile(
                        "mma.sync.aligned.m16n8k8.row.col.f32.tf32.tf32.f32 "
                        "{%0,%1,%2,%3}, {%4,%5,%6,%7}, {%8,%9}, {%0,%1,%2,%3};"
                        : "+f"(acc[mi][ni][0]), "+f"(acc[mi][ni][1]),
                          "+f"(acc[mi][ni][2]), "+f"(acc[mi][ni][3])
                        : "r"(a[mi][0]), "r"(a[mi][1]), "r"(a[mi][2]), "r"(a[mi][3]),
                          "r"(b[ni][0]), "r"(b[ni][1]));
                }
        }
        __syncthreads();
    }

    {
        float* Dz = g_D[bz];
        #pragma unroll
        for (int mi = 0; mi < 2; mi++) {
            #pragma unroll
            for (int ni = 0; ni < 4; ni++) {
                int r = by * BM + wm * 32 + mi * 16 + g;
                int c = bx * BN + wn * 32 + ni * 8 + 2 * tig;
                *(float2*)&Dz[r * BATCH + c]       = make_float2(acc[mi][ni][0], acc[mi][ni][1]);
                *(float2*)&Dz[(r + 8) * BATCH + c] = make_float2(acc[mi][ni][2], acc[mi][ni][3]);
            }
        }
    }

    // ---------------- Grid-wide sync (monotonic counter, replay-safe) ------
    __threadfence();            // make this thread's D stores GPU-visible
    __syncthreads();            // all warps of CTA done
    if (tid == 0) {
        unsigned t = atomicAdd(&g_cnt, 1u);
        unsigned target = ((t >> 7) + 1u) << 7;   // next multiple of NCTA=128
        while (*(volatile unsigned*)&g_cnt < target) { }
        __threadfence();        // acquire
    }
    __syncthreads();

    // ---------------- Phase 2: 4 anchors per CTA ----------------
    const int cta = bx + 4 * (by + 8 * bz);       // 0..127
    const int c0  = 2 * tid;

    if (tid < 4) npos[tid] = 0;
    __syncthreads();

    // rowD for 4 anchors: 16 independent L2 loads (bypass L1 with ldcg).
    float2 rv[4];
    #pragma unroll
    for (int a = 0; a < 4; a++) {
        int i = cta * 4 + a;
        float2 s = make_float2(0.f, 0.f);
        #pragma unroll
        for (int z = 0; z < KSPLIT; z++) {
            float2 v = __ldcg((const float2*)&g_D[z][i * BATCH + c0]);
            s.x += v.x; s.y += v.y;
        }
        rv[a] = s;
    }

    const int2 lb = *(const int2*)&lab[c0];
    int   li[4];
    float mui[4];
    #pragma unroll
    for (int a = 0; a < 4; a++) {
        li[a]  = lab[cta * 4 + a];
        mui[a] = mu[li[a]];
    }

    // Positive compaction per anchor (order-free shared-atomic slots).
    #pragma unroll
    for (int a = 0; a < 4; a++) {
        int i = cta * 4 + a;
        if ((c0     != i) && (lb.x == li[a])) {
            int s = atomicAdd(&npos[a], 1); if (s < MAXPOS) posv[a][s] = rv[a].x;
        }
        if ((c0 + 1 != i) && (lb.y == li[a])) {
            int s = atomicAdd(&npos[a], 1); if (s < MAXPOS) posv[a][s] = rv[a].y;
        }
    }
    __syncthreads();

    float s = 0.f;
    #pragma unroll
    for (int a = 0; a < 4; a++) {
        int np = npos[a]; if (np > MAXPOS) np = MAXPOS;
        if (lb.x != li[a]) {
            float b = mui[a] - rv[a].x;
            for (int p = 0; p < np; p++) s += fmaxf(posv[a][p] + b, 0.f);
        }
        if (lb.y != li[a]) {
            float b = mui[a] - rv[a].y;
            for (int p = 0; p < np; p++) s += fmaxf(posv[a][p] + b, 0.f);
        }
    }

    #pragma unroll
    for (int o = 16; o > 0; o >>= 1) s += __shfl_xor_sync(0xffffffffu, s, o);
    if (lane == 0) red[w] = s;
    __syncthreads();
    if (w == 0) {
        float v = (lane < 8) ? red[lane] : 0.f;
        #pragma unroll
        for (int o = 4; o > 0; o >>= 1) v += __shfl_xor_sync(0xffffffffu, v, o);
        if (lane == 0) atomicAdd(out, v);
    }
}

// ---------------------------------------------------------------------------
extern "C" void kernel_launch(void* const* d_in, const int* in_sizes, int n_in,
                              void* d_out, int out_size) {
    const float* X      = (const float*)d_in[0];
    const int*   labels = (const int*)d_in[1];
    const float* mu     = (const float*)d_in[2];
    const float* nv     = (const float*)d_in[3];
    float*       out    = (float*)d_out;

    dim3 grid(BATCH / BN, BATCH / BM, KSPLIT);   // 4 x 8 x 4 = 128 CTAs (one wave)
    fused_loss<<<grid, 256>>>(X, labels, mu, nv, out);
}

// round 8
// speedup vs baseline: 1.3208x; 1.3208x over previous
#include <cuda_runtime.h>
#include <stdint.h>

#define BATCH   512
#define EMB     512
#define NCLS    100

#define KSPLIT  4
#define KSLICE  (EMB / KSPLIT)   // 128
#define BM      64
#define BN      128
#define BK      32
#define MAXPOS  64

// Scratch: 4 K-slices of D (GEMM gets 4x8x4 = 128 CTAs without atomics).
__device__ float g_D[KSPLIT][BATCH * BATCH];

#define CP_ASYNC16(dst_u32, src_ptr) \
    asm volatile("cp.async.ca.shared.global [%0], [%1], 16;" \
                 :: "r"(dst_u32), "l"(src_ptr))
#define CP_COMMIT() asm volatile("cp.async.commit_group;")
#define CP_WAIT(n)  asm volatile("cp.async.wait_group %0;" :: "n"(n))

__device__ __forceinline__ uint32_t smem_u32(const void* p) {
    return (uint32_t)__cvta_generic_to_shared(p);
}

// ---------------------------------------------------------------------------
// Kernel 1: tf32 tensor-core GEMM, D_z = X_slice @ X_slice^T.
// CTA tile 64x128, 8 warps (2x4), warp tile 32x32, mma.m16n8k8.tf32.
// cp.async double-buffered smem pipeline; raw fp32 bits fed to mma.tf32.
// ---------------------------------------------------------------------------
__global__ __launch_bounds__(256) void gemm_xxT_tc(const float* __restrict__ X,
                                                   const float* __restrict__ mu,
                                                   const float* __restrict__ nv,
                                                   float* __restrict__ out) {
    __shared__ uint32_t As[2][BM][36];
    __shared__ uint32_t Bs[2][BN][36];

    const int tid = threadIdx.x;
    const int bx = blockIdx.x;          // N tile (0..3)
    const int by = blockIdx.y;          // M tile (0..7)
    const int bz = blockIdx.z;          // K slice (0..3)
    const int k0 = bz * KSLICE;

    if (bx == 0 && by == 0 && bz == 0 && tid == 0) {
        float s = 0.f;
        for (int c = 0; c < NCLS; c++) s += mu[c] + nv[c];
        out[0] = -s * (1.0f / NCLS);
    }

    const int w    = tid >> 5;
    const int lane = tid & 31;
    const int g    = lane >> 2;
    const int tig  = lane & 3;
    const int wm   = w & 1;
    const int wn   = w >> 1;

    // per-thread copy coords (fixed across tiles)
    const int ar[2] = { (tid)       >> 3, (tid + 256) >> 3 };
    const int ac    = (tid & 7) * 4;
    // B uses 4 chunks of 256
    // issue one k-tile's copies into buffer `buf`
    auto issue_tile = [&](int kt, int buf) {
        #pragma unroll
        for (int l = 0; l < 2; l++) {
            int r = ar[l];
            CP_ASYNC16(smem_u32(&As[buf][r][ac]),
                       &X[(by * BM + r) * EMB + k0 + kt + ac]);
        }
        #pragma unroll
        for (int l = 0; l < 4; l++) {
            int idx = tid + l * 256;
            int r = idx >> 3, c = (idx & 7) * 4;
            CP_ASYNC16(smem_u32(&Bs[buf][r][c]),
                       &X[(bx * BN + r) * EMB + k0 + kt + c]);
        }
        CP_COMMIT();
    };

    float acc[2][4][4] = {};

    issue_tile(0, 0);

    #pragma unroll
    for (int kt4 = 0; kt4 < 4; kt4++) {          // 4 tiles of BK=32
        const int cur = kt4 & 1;
        __syncthreads();                          // prior readers of buf `cur^1` done
        if (kt4 < 3) issue_tile((kt4 + 1) * BK, cur ^ 1);
        if (kt4 < 3) { CP_WAIT(1); } else { CP_WAIT(0); }
        __syncthreads();                          // tile `cur` visible to all warps

        #pragma unroll
        for (int kk = 0; kk < BK; kk += 8) {
            uint32_t a[2][4], b[4][2];
            #pragma unroll
            for (int mi = 0; mi < 2; mi++) {
                int r0 = wm * 32 + mi * 16;
                a[mi][0] = As[cur][r0 + g    ][kk + tig];
                a[mi][1] = As[cur][r0 + g + 8][kk + tig];
                a[mi][2] = As[cur][r0 + g    ][kk + tig + 4];
                a[mi][3] = As[cur][r0 + g + 8][kk + tig + 4];
            }
            #pragma unroll
            for (int ni = 0; ni < 4; ni++) {
                int n0 = wn * 32 + ni * 8;
                b[ni][0] = Bs[cur][n0 + g][kk + tig];
                b[ni][1] = Bs[cur][n0 + g][kk + tig + 4];
            }
            #pragma unroll
            for (int mi = 0; mi < 2; mi++)
                #pragma unroll
                for (int ni = 0; ni < 4; ni++) {
                    asm volatile(
                        "mma.sync.aligned.m16n8k8.row.col.f32.tf32.tf32.f32 "
                        "{%0,%1,%2,%3}, {%4,%5,%6,%7}, {%8,%9}, {%0,%1,%2,%3};"
                        : "+f"(acc[mi][ni][0]), "+f"(acc[mi][ni][1]),
                          "+f"(acc[mi][ni][2]), "+f"(acc[mi][ni][3])
                        : "r"(a[mi][0]), "r"(a[mi][1]), "r"(a[mi][2]), "r"(a[mi][3]),
                          "r"(b[ni][0]), "r"(b[ni][1]));
                }
        }
    }

    float* Dz = g_D[bz];
    #pragma unroll
    for (int mi = 0; mi < 2; mi++) {
        #pragma unroll
        for (int ni = 0; ni < 4; ni++) {
            int r = by * BM + wm * 32 + mi * 16 + g;
            int c = bx * BN + wn * 32 + ni * 8 + 2 * tig;
            *(float2*)&Dz[r * BATCH + c]       = make_float2(acc[mi][ni][0], acc[mi][ni][1]);
            *(float2*)&Dz[(r + 8) * BATCH + c] = make_float2(acc[mi][ni][2], acc[mi][ni][3]);
        }
    }
}

// ---------------------------------------------------------------------------
// Kernel 2: block-per-anchor hinge (512 CTAs = full-wave parallelism),
// minimal barriers, register-resident rowD, shared-atomic compaction.
// (bit-identical to R6 — proven)
// ---------------------------------------------------------------------------
__global__ __launch_bounds__(256) void row_loss(const int* __restrict__ labels,
                                                const float* __restrict__ mu,
                                                float* __restrict__ out) {
    const int i    = blockIdx.x;
    const int tid  = threadIdx.x;
    const int w    = tid >> 5;
    const int lane = tid & 31;

    __shared__ int   lab[BATCH];
    __shared__ float posv[MAXPOS];
    __shared__ int   npos;
    __shared__ float red[8];

    const int c0 = 2 * tid;

    float2 rv = make_float2(0.f, 0.f);
    #pragma unroll
    for (int z = 0; z < KSPLIT; z++) {
        float2 v = *(const float2*)&g_D[z][i * BATCH + c0];
        rv.x += v.x; rv.y += v.y;
    }
    int2 lb = *(const int2*)&labels[c0];
    *(int2*)&lab[c0] = lb;
    if (tid == 0) npos = 0;
    __syncthreads();

    const int   li  = lab[i];
    const float mui = mu[li];

    bool p0 = (c0     != i) && (lb.x == li);
    bool p1 = (c0 + 1 != i) && (lb.y == li);
    if (p0) { int s = atomicAdd(&npos, 1); if (s < MAXPOS) posv[s] = rv.x; }
    if (p1) { int s = atomicAdd(&npos, 1); if (s < MAXPOS) posv[s] = rv.y; }
    __syncthreads();

    int np = npos; if (np > MAXPOS) np = MAXPOS;

    float s = 0.f;
    if (lb.x != li) {
        float b = mui - rv.x;
        for (int p = 0; p < np; p++) s += fmaxf(posv[p] + b, 0.f);
    }
    if (lb.y != li) {
        float b = mui - rv.y;
        for (int p = 0; p < np; p++) s += fmaxf(posv[p] + b, 0.f);
    }

    #pragma unroll
    for (int o = 16; o > 0; o >>= 1) s += __shfl_xor_sync(0xffffffffu, s, o);
    if (lane == 0) red[w] = s;
    __syncthreads();
    if (w == 0) {
        float v = (lane < 8) ? red[lane] : 0.f;
        #pragma unroll
        for (int o = 4; o > 0; o >>= 1) v += __shfl_xor_sync(0xffffffffu, v, o);
        if (lane == 0) atomicAdd(out, v);
    }
}

// ---------------------------------------------------------------------------
extern "C" void kernel_launch(void* const* d_in, const int* in_sizes, int n_in,
                              void* d_out, int out_size) {
    const float* X      = (const float*)d_in[0];
    const int*   labels = (const int*)d_in[1];
    const float* mu     = (const float*)d_in[2];
    const float* nv     = (const float*)d_in[3];
    float*       out    = (float*)d_out;

    dim3 ggrid(BATCH / BN, BATCH / BM, KSPLIT);   // 4 x 8 x 4 = 128 CTAs
    gemm_xxT_tc<<<ggrid, 256>>>(X, mu, nv, out);
    row_loss<<<BATCH, 256>>>(labels, mu, out);
}